// round 5
// baseline (speedup 1.0000x reference)
#include <cuda_runtime.h>
#include <cstdint>

#define NS 512          // number of sites N
#define CHUNK 16        // sites per lane (32 lanes * 16 = 512)
#define WPB 6           // warps (batches) per block
#define THREADS (WPB * 32)

// A coefficients for site n = l*16 + k at idx = k*32 + l, packed as
// 9 floats across two float4 planes + one float plane:
//   a = (c00.x, c00.y, c00.z, c01.x), b4 = (c01.y, c01.z, c11.x, c11.y), s = c11.z
// where cP = (A_xx, A_xy+A_yx, A_yy) for upper-tri element P of M.
__device__ float4 g_A4a[NS];
__device__ float4 g_A4b[NS];
__device__ float  g_A1[NS];

__global__ void prep_A_kernel(const float* __restrict__ mpo) {
    int n = blockIdx.x * blockDim.x + threadIdx.x;
    if (n >= NS) return;
    const float inv = 1.0f / (1.5707963267948966f + 1e-5f); // 1/PI_HALF
    int l = n >> 4, k = n & 15;
    int idx = k * 32 + l;
    float c[9];
    #pragma unroll
    for (int p = 0; p < 3; p++) {
        int li = (p == 2) ? 1 : 0;
        int ri = (p == 0) ? 0 : 1;
        const float* m = mpo + n * 16 + li * 8 + ri * 4; // mpo[n,li,ri,:,:]
        c[p * 3 + 0] = atanf(m[0]) * inv;
        c[p * 3 + 1] = (atanf(m[1]) + atanf(m[2])) * inv;
        c[p * 3 + 2] = atanf(m[3]) * inv;
    }
    g_A4a[idx] = make_float4(c[0], c[1], c[2], c[3]);
    g_A4b[idx] = make_float4(c[4], c[5], c[6], c[7]);
    g_A1[idx]  = c[8];
}

// ||(a,b)|| via rsqrt, safe when a*a+b*b flushes to 0.
__device__ __forceinline__ float safe_norm(float a, float b) {
    float r2 = fmaf(a, a, b * b);
    float nm = r2 * rsqrtf(r2);
    return (r2 > 0.f) ? nm : 0.f;
}

__global__ void __launch_bounds__(THREADS, 5)
tdvp_kernel(const float* __restrict__ x,
            const float* __restrict__ scale_p,
            float* __restrict__ out,
            int B)
{
    __shared__ float4 sA4a[NS];           //  8192 B
    __shared__ float4 sA4b[NS];           //  8192 B
    __shared__ float  sA1[NS];            //  2048 B
    __shared__ float2 sX[WPB][NS];        // 24576 B  (total 43008 B)

    int tid = threadIdx.x;
    for (int i = tid; i < NS; i += THREADS) {
        sA4a[i] = g_A4a[i];
        sA4b[i] = g_A4b[i];
        sA1[i]  = g_A1[i];
    }
    __syncthreads();

    const int lane = tid & 31;
    const int warp = tid >> 5;
    const int b = blockIdx.x * WPB + warp;
    if (b >= B) return;

    const float scale = __ldg(scale_p);

    // ---- Stage x: coalesced float4 global loads -> transposed swizzled smem.
    // Site n = l*16 + k owned by lane l; stored at sx[k*32 + (l ^ k)] as float2.
    float2* sx = sX[warp];
    {
        const float4* xg = reinterpret_cast<const float4*>(x + (size_t)b * (NS * 2));
        #pragma unroll
        for (int it = 0; it < 8; it++) {
            float4 v = xg[it * 32 + lane];
            int n0 = (it * 32 + lane) * 2;       // first of two sites in this float4
            int l0 = n0 >> 4;
            int k0 = n0 & 15;
            sx[k0 * 32 + (l0 ^ k0)] = make_float2(v.x, v.y);
            sx[(k0 + 1) * 32 + (l0 ^ (k0 + 1))] = make_float2(v.z, v.w);
        }
        __syncwarp();
    }

    const int nbase = lane * CHUNK;

    // ---- Pass A: normalize x, build upper-tri M = (m00,m01,m11) per site,
    //              and lane-local chunk aggregate (ca,cb,cd).
    float M00[CHUNK], M01[CHUNK], M11[CHUNK];
    float ca = 1.f, cb = 0.f, cd = 1.f;
    #pragma unroll
    for (int k = 0; k < CHUNK; k++) {
        float2 xv = sx[k * 32 + (lane ^ k)];
        float rnx = rsqrtf(fmaf(xv.x, xv.x, xv.y * xv.y));
        float u0 = xv.x * rnx, u1 = xv.y * rnx;
        float p = u0 * u0, q = u0 * u1, r = u1 * u1;
        const int ai = k * 32 + lane;
        float4 a4 = sA4a[ai];
        float4 b4 = sA4b[ai];
        float  s1 = sA1[ai];
        float m00 = fmaf(p, a4.x, fmaf(q, a4.y, r * a4.z));
        float m01 = fmaf(p, a4.w, fmaf(q, b4.x, r * b4.y));
        float m11 = fmaf(p, b4.z, fmaf(q, b4.w, r * s1));
        M00[k] = m00; M01[k] = m01; M11[k] = m11;
        float na = ca * m00;
        float nb = fmaf(ca, m01, cb * m11);
        cd = cd * m11;
        ca = na; cb = nb;
    }
    __syncwarp();   // sX reads done; buffer reused as scratch below

    // ---- Warp Kogge-Stone inclusive PREFIX scan of chunk aggregates.
    float pa = ca, pb = cb, pd = cd;
    #pragma unroll
    for (int off = 1; off < 32; off <<= 1) {
        float na = __shfl_up_sync(0xffffffffu, pa, off);
        float nb = __shfl_up_sync(0xffffffffu, pb, off);
        float nd = __shfl_up_sync(0xffffffffu, pd, off);
        if (lane >= off) {
            float ta = na * pa;
            float tb = fmaf(na, pb, nb * pd);
            float td = nd * pd;
            pa = ta; pb = tb; pd = td;
        }
    }
    // Full-chain product entry T[0,1] (lane 31 inclusive prefix).
    float T01 = __shfl_sync(0xffffffffu, pb, 31);
    float ea = __shfl_up_sync(0xffffffffu, pa, 1);
    float eb = __shfl_up_sync(0xffffffffu, pb, 1);
    if (lane == 0) { ea = 1.f; eb = 0.f; }

    // ---- Warp inclusive SUFFIX scan; exclusive tail (col1 only needed).
    float sa = ca, sb2 = cb, sd2 = cd;
    #pragma unroll
    for (int off = 1; off < 32; off <<= 1) {
        float na = __shfl_down_sync(0xffffffffu, sa, off);
        float nb = __shfl_down_sync(0xffffffffu, sb2, off);
        float nd = __shfl_down_sync(0xffffffffu, sd2, off);
        if (lane + off < 32) {
            float ta = sa * na;
            float tb = fmaf(sa, nb, sb2 * nd);
            float td = sd2 * nd;
            sa = ta; sb2 = tb; sd2 = td;
        }
    }
    float esb = __shfl_down_sync(0xffffffffu, sb2, 1);
    float esd = __shfl_down_sync(0xffffffffu, sd2, 1);
    if (lane == 31) { esb = 0.f; esd = 1.f; }

    // ---- Backward walk: rn = ||S[n+1] col1|| + eps (exact 1 at n=N-1),
    //      stored to reused per-warp smem scratch (conflict-free [k*32+lane]).
    float* rnS = reinterpret_cast<float*>(sx);
    {
        float Sb = esb, Sd = esd;
        #pragma unroll
        for (int k = CHUNK - 1; k >= 0; k--) {
            float rv = (nbase + k == NS - 1) ? 1.0f : (safe_norm(Sb, Sd) + 1e-6f);
            rnS[k * 32 + lane] = rv;
            float nSb = fmaf(M00[k], Sb, M01[k] * Sd);
            Sd = M11[k] * Sd;
            Sb = nSb;
        }
    }

    // ---- Forward walk: pn = ||P[n-1] row0|| + eps (exact 1 at n=0);
    //      w = 1/(pn*rn); y[n] = T01 * w. Store w back to scratch.
    float ra = ea, rb = eb;
    float sumw = 0.f;
    #pragma unroll
    for (int k = 0; k < CHUNK; k++) {
        float pn = (nbase + k == 0) ? 1.0f : (safe_norm(ra, rb) + 1e-6f);
        float w = __fdividef(1.0f, pn * rnS[k * 32 + lane]);
        rnS[k * 32 + lane] = w;
        sumw += w;
        float nra = ra * M00[k];
        rb = fmaf(ra, M01[k], rb * M11[k]);
        ra = nra;
    }

    // ---- Reduce sum of w; fold relu + L1 normalization into one factor.
    #pragma unroll
    for (int off = 16; off; off >>= 1)
        sumw += __shfl_xor_sync(0xffffffffu, sumw, off);

    // o[n] = relu(scale*T01*w): w > 0, so sign is uniform per batch.
    float c = scale * T01;
    float f = (c > 0.f) ? __fdividef(c, fmaf(c, sumw, 1e-6f)) : 0.f;

    float* ob = out + (size_t)b * NS + nbase;
    #pragma unroll
    for (int k = 0; k < CHUNK; k += 4) {
        float4 v;
        v.x = rnS[(k + 0) * 32 + lane] * f;
        v.y = rnS[(k + 1) * 32 + lane] * f;
        v.z = rnS[(k + 2) * 32 + lane] * f;
        v.w = rnS[(k + 3) * 32 + lane] * f;
        *reinterpret_cast<float4*>(ob + k) = v;
    }
}

extern "C" void kernel_launch(void* const* d_in, const int* in_sizes, int n_in,
                              void* d_out, int out_size) {
    const float* x     = (const float*)d_in[0]; // (B, N, 2)
    const float* mpo   = (const float*)d_in[1]; // (N, 2, 2, 2, 2)
    const float* scale = (const float*)d_in[2]; // scalar
    float* out = (float*)d_out;                 // (B, N)

    int B = in_sizes[0] / (NS * 2);

    prep_A_kernel<<<(NS + 255) / 256, 256>>>(mpo);
    int blocks = (B + WPB - 1) / WPB;
    tdvp_kernel<<<blocks, THREADS>>>(x, scale, out, B);
}